// round 1
// baseline (speedup 1.0000x reference)
#include <cuda_runtime.h>
#include <cuda_bf16.h>

// ActuatorNet: y = fc_out( softsign^19( hidden ) ( softsign( x@W1 + b1 ) ) )
// x: [B,6] f32, W1: [6,32], b1: [32], Wh: [19,32,32], bh: [19,32],
// Wout: [32,1], bout: [1]  ->  out: [B,1] f32
//
// Strategy (round 0 baseline): one row per thread, all weights in dynamic
// shared memory (broadcast LDS.128 reads), h[32]/acc[32] in registers,
// fully unrolled 32x32 inner product per layer, layer loop rolled.

#define NTHREADS 256

// smem layout (floats)
#define S_W1    0        // 6*32   = 192
#define S_B1    192      // 32
#define S_WH    224      // 19*32*32 = 19456
#define S_BH    19680    // 19*32  = 608
#define S_WOUT  20288    // 32
#define S_BOUT  20320    // 1
#define S_TOTAL 20321    // floats -> 81284 bytes

__global__ __launch_bounds__(NTHREADS, 2)
void actuator_mlp_kernel(const float* __restrict__ x,
                         const float* __restrict__ W1,
                         const float* __restrict__ b1,
                         const float* __restrict__ Wh,
                         const float* __restrict__ bh,
                         const float* __restrict__ Wout,
                         const float* __restrict__ bout,
                         float* __restrict__ out,
                         int B)
{
    extern __shared__ float s[];

    // Cooperative weight staging (weights are tiny & L2-resident: 4096 CTAs
    // re-reading 79KB hits L2 every time).
    int t = threadIdx.x;
    for (int i = t; i < 192;   i += NTHREADS) s[S_W1 + i]   = W1[i];
    for (int i = t; i < 32;    i += NTHREADS) s[S_B1 + i]   = b1[i];
    for (int i = t; i < 19456; i += NTHREADS) s[S_WH + i]   = Wh[i];
    for (int i = t; i < 608;   i += NTHREADS) s[S_BH + i]   = bh[i];
    for (int i = t; i < 32;    i += NTHREADS) s[S_WOUT + i] = Wout[i];
    if (t == 0) s[S_BOUT] = bout[0];
    __syncthreads();

    int row = blockIdx.x * NTHREADS + t;
    if (row >= B) return;

    // ---- load input row (6 floats) ----
    float xin[6];
    {
        const float* xr = x + (long long)row * 6;
        #pragma unroll
        for (int i = 0; i < 6; i++) xin[i] = __ldg(xr + i);
    }

    float h[32];

    // ---- layer 1: [6] -> [32] + softsign ----
    {
        #pragma unroll
        for (int j = 0; j < 32; j++) h[j] = s[S_B1 + j];
        #pragma unroll
        for (int i = 0; i < 6; i++) {
            float xi = xin[i];
            const float4* wr = reinterpret_cast<const float4*>(s + S_W1 + i * 32);
            #pragma unroll
            for (int j4 = 0; j4 < 8; j4++) {
                float4 w = wr[j4];
                h[4 * j4 + 0] += xi * w.x;
                h[4 * j4 + 1] += xi * w.y;
                h[4 * j4 + 2] += xi * w.z;
                h[4 * j4 + 3] += xi * w.w;
            }
        }
        #pragma unroll
        for (int j = 0; j < 32; j++)
            h[j] = __fdividef(h[j], 1.0f + fabsf(h[j]));
    }

    // ---- 19 hidden layers: [32] -> [32] + softsign ----
    for (int l = 0; l < 19; l++) {
        const float* Wl = s + S_WH + l * 1024;
        const float* bl = s + S_BH + l * 32;
        float acc[32];
        #pragma unroll
        for (int j = 0; j < 32; j++) acc[j] = bl[j];
        #pragma unroll
        for (int i = 0; i < 32; i++) {
            float hi = h[i];
            const float4* wr = reinterpret_cast<const float4*>(Wl + i * 32);
            #pragma unroll
            for (int j4 = 0; j4 < 8; j4++) {
                float4 w = wr[j4];
                acc[4 * j4 + 0] += hi * w.x;
                acc[4 * j4 + 1] += hi * w.y;
                acc[4 * j4 + 2] += hi * w.z;
                acc[4 * j4 + 3] += hi * w.w;
            }
        }
        #pragma unroll
        for (int j = 0; j < 32; j++)
            h[j] = __fdividef(acc[j], 1.0f + fabsf(acc[j]));
    }

    // ---- output layer: [32] -> [1], no activation ----
    float o = s[S_BOUT];
    #pragma unroll
    for (int i = 0; i < 32; i++) o += h[i] * s[S_WOUT + i];
    out[row] = o;
}

extern "C" void kernel_launch(void* const* d_in, const int* in_sizes, int n_in,
                              void* d_out, int out_size)
{
    const float* x    = (const float*)d_in[0];
    const float* W1   = (const float*)d_in[1];
    const float* b1   = (const float*)d_in[2];
    const float* Wh   = (const float*)d_in[3];
    const float* bh   = (const float*)d_in[4];
    const float* Wout = (const float*)d_in[5];
    const float* bout = (const float*)d_in[6];
    float* out = (float*)d_out;

    int B = in_sizes[0] / 6;
    size_t smem_bytes = (size_t)S_TOTAL * sizeof(float);  // 81284 B > 48KB -> opt-in

    cudaFuncSetAttribute(actuator_mlp_kernel,
                         cudaFuncAttributeMaxDynamicSharedMemorySize,
                         (int)smem_bytes);

    int grid = (B + NTHREADS - 1) / NTHREADS;
    actuator_mlp_kernel<<<grid, NTHREADS, smem_bytes>>>(
        x, W1, b1, Wh, bh, Wout, bout, out, B);
}

// round 2
// speedup vs baseline: 1.4867x; 1.4867x over previous
#include <cuda_runtime.h>
#include <cuda_bf16.h>

// ActuatorNet fused MLP, round 2: packed fp32x2 FMA (FFMA2) + 2 rows/thread.
//
// Packing: output-neuron pairs. acc2[j2] = (acc[2*j2], acc[2*j2+1]) so the
// FFMA2 weight operand (w[i][2j], w[i][2j+1]) is a naturally contiguous
// 8-byte pair in smem -> loaded as ulonglong2 (LDS.128 = 2 packed operands),
// zero packing instructions for weights. Only the per-row activation h[i]
// needs duplication into (h,h): 2 mov.b64 per k-index.
//
// 2 rows per thread => each weight LDS serves both rows (halves L1 traffic
// per row, which was 89.9%-of-peak bound in round 1).

#define NTHREADS 256

// smem layout (floats)
#define S_W1    0        // 6*32   = 192
#define S_B1    192      // 32
#define S_WH    224      // 19*32*32 = 19456
#define S_BH    19680    // 19*32  = 608
#define S_WOUT  20288    // 32
#define S_BOUT  20320    // 1
#define S_TOTAL 20321    // floats -> 81284 bytes

typedef unsigned long long u64;

// (v, v) packed f32x2
__device__ __forceinline__ u64 dup2(float v) {
    u64 r;
    asm("mov.b64 %0, {%1, %1};" : "=l"(r) : "f"(v));
    return r;
}

// d = a * b + d, packed 2x fp32
__device__ __forceinline__ void fma2(u64& d, u64 a, u64 b) {
    asm("fma.rn.f32x2 %0, %1, %2, %0;" : "+l"(d) : "l"(a), "l"(b));
}

__device__ __forceinline__ float2 unpk(u64 v) {
    float2 f;
    asm("mov.b64 {%0, %1}, %2;" : "=f"(f.x), "=f"(f.y) : "l"(v));
    return f;
}

__device__ __forceinline__ float softsign(float v) {
    return __fdividef(v, 1.0f + fabsf(v));
}

__global__ __launch_bounds__(NTHREADS, 1)
void actuator_mlp_kernel(const float* __restrict__ x,
                         const float* __restrict__ W1,
                         const float* __restrict__ b1,
                         const float* __restrict__ Wh,
                         const float* __restrict__ bh,
                         const float* __restrict__ Wout,
                         const float* __restrict__ bout,
                         float* __restrict__ out,
                         int B)
{
    extern __shared__ float s[];

    int t = threadIdx.x;
    for (int i = t; i < 192;   i += NTHREADS) s[S_W1 + i]   = W1[i];
    for (int i = t; i < 32;    i += NTHREADS) s[S_B1 + i]   = b1[i];
    for (int i = t; i < 19456; i += NTHREADS) s[S_WH + i]   = Wh[i];
    for (int i = t; i < 608;   i += NTHREADS) s[S_BH + i]   = bh[i];
    for (int i = t; i < 32;    i += NTHREADS) s[S_WOUT + i] = Wout[i];
    if (t == 0) s[S_BOUT] = bout[0];
    __syncthreads();

    int rowA = (blockIdx.x * NTHREADS + t) * 2;
    if (rowA >= B) return;
    int rowB = min(rowA + 1, B - 1);  // odd-B safe: duplicates last row

    // ---- load input rows (6 floats each) ----
    float xa[6], xb[6];
    {
        const float* pa = x + (long long)rowA * 6;
        const float* pb = x + (long long)rowB * 6;
        #pragma unroll
        for (int i = 0; i < 6; i++) { xa[i] = __ldg(pa + i); xb[i] = __ldg(pb + i); }
    }

    float hA[32], hB[32];        // scalar activations per row
    u64 accA[16], accB[16];      // packed output-pair accumulators

    // ---- layer 1: [6] -> [32] + softsign ----
    {
        const ulonglong2* bp = reinterpret_cast<const ulonglong2*>(s + S_B1);
        #pragma unroll
        for (int q = 0; q < 8; q++) {
            ulonglong2 b = bp[q];
            accA[2 * q] = b.x; accA[2 * q + 1] = b.y;
            accB[2 * q] = b.x; accB[2 * q + 1] = b.y;
        }
        #pragma unroll
        for (int i = 0; i < 6; i++) {
            u64 ma = dup2(xa[i]);
            u64 mb = dup2(xb[i]);
            const ulonglong2* wr = reinterpret_cast<const ulonglong2*>(s + S_W1 + i * 32);
            #pragma unroll
            for (int q = 0; q < 8; q++) {
                ulonglong2 w = wr[q];
                fma2(accA[2 * q], ma, w.x);
                fma2(accA[2 * q + 1], ma, w.y);
                fma2(accB[2 * q], mb, w.x);
                fma2(accB[2 * q + 1], mb, w.y);
            }
        }
        #pragma unroll
        for (int j2 = 0; j2 < 16; j2++) {
            float2 a = unpk(accA[j2]);
            float2 b = unpk(accB[j2]);
            hA[2 * j2] = softsign(a.x); hA[2 * j2 + 1] = softsign(a.y);
            hB[2 * j2] = softsign(b.x); hB[2 * j2 + 1] = softsign(b.y);
        }
    }

    // ---- 19 hidden layers: [32] -> [32] + softsign ----
    for (int l = 0; l < 19; l++) {
        const float* Wl = s + S_WH + l * 1024;
        const ulonglong2* bp = reinterpret_cast<const ulonglong2*>(s + S_BH + l * 32);
        #pragma unroll
        for (int q = 0; q < 8; q++) {
            ulonglong2 b = bp[q];
            accA[2 * q] = b.x; accA[2 * q + 1] = b.y;
            accB[2 * q] = b.x; accB[2 * q + 1] = b.y;
        }
        #pragma unroll
        for (int i = 0; i < 32; i++) {
            u64 ma = dup2(hA[i]);
            u64 mb = dup2(hB[i]);
            const ulonglong2* wr = reinterpret_cast<const ulonglong2*>(Wl + i * 32);
            #pragma unroll
            for (int q = 0; q < 8; q++) {
                ulonglong2 w = wr[q];
                fma2(accA[2 * q], ma, w.x);
                fma2(accA[2 * q + 1], ma, w.y);
                fma2(accB[2 * q], mb, w.x);
                fma2(accB[2 * q + 1], mb, w.y);
            }
        }
        #pragma unroll
        for (int j2 = 0; j2 < 16; j2++) {
            float2 a = unpk(accA[j2]);
            float2 b = unpk(accB[j2]);
            hA[2 * j2] = softsign(a.x); hA[2 * j2 + 1] = softsign(a.y);
            hB[2 * j2] = softsign(b.x); hB[2 * j2 + 1] = softsign(b.y);
        }
    }

    // ---- output layer: [32] -> [1], no activation ----
    float oA = s[S_BOUT];
    float oB = oA;
    #pragma unroll
    for (int i = 0; i < 32; i++) {
        float w = s[S_WOUT + i];
        oA += hA[i] * w;
        oB += hB[i] * w;
    }
    out[rowA] = oA;
    out[rowB] = oB;
}

extern "C" void kernel_launch(void* const* d_in, const int* in_sizes, int n_in,
                              void* d_out, int out_size)
{
    const float* x    = (const float*)d_in[0];
    const float* W1   = (const float*)d_in[1];
    const float* b1   = (const float*)d_in[2];
    const float* Wh   = (const float*)d_in[3];
    const float* bh   = (const float*)d_in[4];
    const float* Wout = (const float*)d_in[5];
    const float* bout = (const float*)d_in[6];
    float* out = (float*)d_out;

    int B = in_sizes[0] / 6;
    size_t smem_bytes = (size_t)S_TOTAL * sizeof(float);

    cudaFuncSetAttribute(actuator_mlp_kernel,
                         cudaFuncAttributeMaxDynamicSharedMemorySize,
                         (int)smem_bytes);

    int rows_per_cta = NTHREADS * 2;
    int grid = (B + rows_per_cta - 1) / rows_per_cta;
    actuator_mlp_kernel<<<grid, NTHREADS, smem_bytes>>>(
        x, W1, b1, Wh, bh, Wout, bout, out, B);
}

// round 4
// speedup vs baseline: 3.1473x; 2.1170x over previous
#include <cuda_runtime.h>
#include <cuda_bf16.h>
#include <cstdint>

// ActuatorNet via warp-level mma.sync (HMMA, portable PTX -> works on the
// generic compute_103 target; tcgen05 is sm_103a-only and ptxas rejects it).
//
// Numerics: bf16 2-term split of activations (hi+lo) and weights (hi+lo),
// D = Ahi*Whi + Alo*Whi + Ahi*Wlo with f32 accumulation (drop lo*lo term).
//
// Layout trick: for mma.m16n8k16, the D fragment of four n8 blocks equals
// the A fragment of the next layer's two k16 steps (same thread<->element
// map), so activations chain across all 19 layers purely in registers.
// Weights are pre-staged into smem in per-thread fragment order so each
// layer needs only 16 conflict-free LDS.64 (+4 LDS.64 of bias, folded
// into the accumulator init).

#define NTHREADS 256
#define NWARPS   8

// smem layout (bytes)
#define SM_FRAG   0                      // 19*16*32 u64 = 77824
#define SM_W1     77824                  // 192 f32
#define SM_B1     (SM_W1 + 768)          // 32 f32
#define SM_BH     (SM_B1 + 128)          // 19*32 f32 = 2432
#define SM_WOUT   (SM_BH + 2432)         // 32 f32
#define SM_BOUT   (SM_WOUT + 128)        // 1 f32
#define SM_TOTAL  (SM_BOUT + 16)         // ~81.2 KB

typedef unsigned long long u64;

__device__ __forceinline__ uint32_t cvt_bf16x2(float hi_elem, float lo_elem) {
    uint32_t r;   // packs lo_elem into bits[0:16), hi_elem into bits[16:32)
    asm("cvt.rn.bf16x2.f32 %0, %1, %2;" : "=r"(r) : "f"(hi_elem), "f"(lo_elem));
    return r;
}

__device__ __forceinline__ void mma_bf16(float d[4],
                                         uint32_t a0, uint32_t a1,
                                         uint32_t a2, uint32_t a3,
                                         uint32_t b0, uint32_t b1) {
    asm volatile(
        "mma.sync.aligned.m16n8k16.row.col.f32.bf16.bf16.f32 "
        "{%0,%1,%2,%3}, {%4,%5,%6,%7}, {%8,%9}, {%0,%1,%2,%3};"
        : "+f"(d[0]), "+f"(d[1]), "+f"(d[2]), "+f"(d[3])
        : "r"(a0), "r"(a1), "r"(a2), "r"(a3), "r"(b0), "r"(b1));
}

__device__ __forceinline__ float softsign_f(float v) {
    return __fdividef(v, 1.0f + fabsf(v));
}

__global__ __launch_bounds__(NTHREADS, 2)
void actuator_hmma_kernel(const float* __restrict__ x,
                          const float* __restrict__ W1,
                          const float* __restrict__ b1,
                          const float* __restrict__ Wh,
                          const float* __restrict__ bh,
                          const float* __restrict__ Wout,
                          const float* __restrict__ bout,
                          float* __restrict__ out,
                          int B, int ntiles)
{
    extern __shared__ char smem[];
    u64*   sFRAG = (u64*)(smem + SM_FRAG);
    float* sW1   = (float*)(smem + SM_W1);
    float* sB1   = (float*)(smem + SM_B1);
    float* sBH   = (float*)(smem + SM_BH);
    float* sWOUT = (float*)(smem + SM_WOUT);
    float* sBOUT = (float*)(smem + SM_BOUT);

    const int tid = threadIdx.x;

    // ---- stage small fp32 params ----
    for (int i = tid; i < 192; i += NTHREADS) sW1[i] = W1[i];
    for (int i = tid; i < 32;  i += NTHREADS) sB1[i] = b1[i];
    for (int i = tid; i < 608; i += NTHREADS) sBH[i] = bh[i];
    for (int i = tid; i < 32;  i += NTHREADS) sWOUT[i] = Wout[i];
    if (tid == 0) sBOUT[0] = bout[0];

    // ---- stage hidden weights as per-thread B fragments (hi & lo) ----
    // slot index = ((l*16 + combo)*32 + lane), combo = term*8 + ks*4 + nb
    // B frag (col-major 16x8): col = nb*8 + lane/4; q = lane%4
    //   rb0 = bf16x2( W[k0+1][col], W[k0][col] ),  k0 = ks*16 + 2q
    //   rb1 = bf16x2( W[k0+9][col], W[k0+8][col] )
    for (int idx = tid; idx < 19 * 16 * 32; idx += NTHREADS) {
        int lane  = idx & 31;
        int combo = (idx >> 5) & 15;
        int l     = idx >> 9;
        int nb    = combo & 3;
        int ks    = (combo >> 2) & 1;
        int term  = combo >> 3;           // 0 = hi, 1 = lo
        int col   = nb * 8 + (lane >> 2);
        int q     = lane & 3;
        int k0    = ks * 16 + q * 2;

        const float* Wl = Wh + l * 1024;
        float w[4];
        w[0] = Wl[(k0 + 0) * 32 + col];
        w[1] = Wl[(k0 + 1) * 32 + col];
        w[2] = Wl[(k0 + 8) * 32 + col];
        w[3] = Wl[(k0 + 9) * 32 + col];

        uint32_t rb0, rb1;
        if (term == 0) {
            rb0 = cvt_bf16x2(w[1], w[0]);
            rb1 = cvt_bf16x2(w[3], w[2]);
        } else {
            float r0 = w[0] - __bfloat162float(__float2bfloat16(w[0]));
            float r1 = w[1] - __bfloat162float(__float2bfloat16(w[1]));
            float r2 = w[2] - __bfloat162float(__float2bfloat16(w[2]));
            float r3 = w[3] - __bfloat162float(__float2bfloat16(w[3]));
            rb0 = cvt_bf16x2(r1, r0);
            rb1 = cvt_bf16x2(r3, r2);
        }
        sFRAG[idx] = ((u64)rb1 << 32) | rb0;
    }
    __syncthreads();

    const int wid  = tid >> 5;
    const int lane = tid & 31;
    const int g    = lane >> 2;   // group id: row offset
    const int q    = lane & 3;    // col pair within n8 block

    const float bias_out = sBOUT[0];

    for (int tile = blockIdx.x * NWARPS + wid; tile < ntiles;
         tile += gridDim.x * NWARPS) {

        int r0 = tile * 16 + g;       // rows r0 and r0+8
        int r1 = r0 + 8;
        int r0c = min(r0, B - 1);
        int r1c = min(r1, B - 1);

        // act layout matches D fragments: act[nb*4 + {0,1,2,3}] =
        //   h[r0][nb*8+2q], h[r0][nb*8+2q+1], h[r1][...], h[r1][...+1]
        float act[16];

        // ---- layer 1 (6 -> 32), fp32 SIMT ----
        {
            float xa[6], xb[6];
            const float* pa = x + (long long)r0c * 6;
            const float* pb = x + (long long)r1c * 6;
            #pragma unroll
            for (int i = 0; i < 6; i++) { xa[i] = __ldg(pa + i); xb[i] = __ldg(pb + i); }
            #pragma unroll
            for (int nb = 0; nb < 4; nb++) {
                int c0 = nb * 8 + q * 2;
                float s00 = sB1[c0], s01 = sB1[c0 + 1];
                float s10 = s00,     s11 = s01;
                #pragma unroll
                for (int i = 0; i < 6; i++) {
                    float w0 = sW1[i * 32 + c0], w1 = sW1[i * 32 + c0 + 1];
                    s00 += xa[i] * w0; s01 += xa[i] * w1;
                    s10 += xb[i] * w0; s11 += xb[i] * w1;
                }
                act[nb * 4 + 0] = softsign_f(s00);
                act[nb * 4 + 1] = softsign_f(s01);
                act[nb * 4 + 2] = softsign_f(s10);
                act[nb * 4 + 3] = softsign_f(s11);
            }
        }

        // ---- 19 hidden layers via HMMA ----
        for (int l = 0; l < 19; l++) {
            // split activations into bf16 hi/lo A fragments
            // pair p packs act[2p], act[2p+1]; A reg [ks*4+i] = pair (ks*4+i)
            uint32_t ahi[8], alo[8];
            #pragma unroll
            for (int p = 0; p < 8; p++) {
                float e0 = act[2 * p], e1 = act[2 * p + 1];
                uint32_t hp = cvt_bf16x2(e1, e0);
                float f0 = __uint_as_float(hp << 16);
                float f1 = __uint_as_float(hp & 0xFFFF0000u);
                ahi[p] = hp;
                alo[p] = cvt_bf16x2(e1 - f1, e0 - f0);
            }

            // load B fragments (hi: combos 0..7, lo: combos 8..15)
            u64 Bhi[8], Blo[8];
            const u64* fl = sFRAG + (l * 16) * 32 + lane;
            #pragma unroll
            for (int cidx = 0; cidx < 8; cidx++) Bhi[cidx] = fl[cidx * 32];
            #pragma unroll
            for (int cidx = 0; cidx < 8; cidx++) Blo[cidx] = fl[(8 + cidx) * 32];

            // init accumulators with bias (c0==c2, c1==c3 share columns)
            float d[4][4];
            const float2* blp = (const float2*)(sBH + l * 32);
            #pragma unroll
            for (int nb = 0; nb < 4; nb++) {
                float2 bb = blp[nb * 4 + q];
                d[nb][0] = bb.x; d[nb][1] = bb.y;
                d[nb][2] = bb.x; d[nb][3] = bb.y;
            }

            #pragma unroll
            for (int ks = 0; ks < 2; ks++) {
                uint32_t a0 = ahi[ks*4+0], a1 = ahi[ks*4+1],
                         a2 = ahi[ks*4+2], a3 = ahi[ks*4+3];
                uint32_t l0 = alo[ks*4+0], l1 = alo[ks*4+1],
                         l2 = alo[ks*4+2], l3 = alo[ks*4+3];
                #pragma unroll
                for (int nb = 0; nb < 4; nb++) {
                    u64 wh = Bhi[ks*4+nb], wl = Blo[ks*4+nb];
                    uint32_t bh0 = (uint32_t)wh, bh1 = (uint32_t)(wh >> 32);
                    uint32_t bl0 = (uint32_t)wl, bl1 = (uint32_t)(wl >> 32);
                    mma_bf16(d[nb], a0, a1, a2, a3, bh0, bh1);  // hi*Whi
                    mma_bf16(d[nb], l0, l1, l2, l3, bh0, bh1);  // lo*Whi
                    mma_bf16(d[nb], a0, a1, a2, a3, bl0, bl1);  // hi*Wlo
                }
            }

            #pragma unroll
            for (int i = 0; i < 16; i++)
                act[i] = softsign_f(d[i >> 2][i & 3]);
        }

        // ---- output layer (32 -> 1) + quad reduction ----
        float po0 = 0.0f, po1 = 0.0f;
        #pragma unroll
        for (int nb = 0; nb < 4; nb++) {
            int c0 = nb * 8 + q * 2;
            float w0 = sWOUT[c0], w1 = sWOUT[c0 + 1];
            po0 += act[nb * 4 + 0] * w0 + act[nb * 4 + 1] * w1;
            po1 += act[nb * 4 + 2] * w0 + act[nb * 4 + 3] * w1;
        }
        po0 += __shfl_xor_sync(0xFFFFFFFFu, po0, 1);
        po0 += __shfl_xor_sync(0xFFFFFFFFu, po0, 2);
        po1 += __shfl_xor_sync(0xFFFFFFFFu, po1, 1);
        po1 += __shfl_xor_sync(0xFFFFFFFFu, po1, 2);
        if (q == 0) {
            if (r0 < B) out[r0] = po0 + bias_out;
            if (r1 < B) out[r1] = po1 + bias_out;
        }
    }
}

extern "C" void kernel_launch(void* const* d_in, const int* in_sizes, int n_in,
                              void* d_out, int out_size)
{
    const float* x    = (const float*)d_in[0];
    const float* W1   = (const float*)d_in[1];
    const float* b1   = (const float*)d_in[2];
    const float* Wh   = (const float*)d_in[3];
    const float* bh   = (const float*)d_in[4];
    const float* Wout = (const float*)d_in[5];
    const float* bout = (const float*)d_in[6];
    float* out = (float*)d_out;

    int B = in_sizes[0] / 6;
    int ntiles = (B + 15) / 16;

    cudaFuncSetAttribute(actuator_hmma_kernel,
                         cudaFuncAttributeMaxDynamicSharedMemorySize, SM_TOTAL);

    int grid = 296;   // persistent: 2 CTAs/SM x 148 SMs, grid-stride over tiles
    actuator_hmma_kernel<<<grid, NTHREADS, SM_TOTAL>>>(
        x, W1, b1, Wh, bh, Wout, bout, out, B, ntiles);
}